// round 1
// baseline (speedup 1.0000x reference)
#include <cuda_runtime.h>
#include <math.h>
#include <stdint.h>

#define NL 4
#define DM 768
#define DI 1536
#define DS 16
#define DR 48
#define KC 4
#define VV 32000
#define BB 2
#define SS 2048
#define MROWS (BB*SS)          /* 4096 */
#define NDBC (DR+2*DS)         /* 80 */

// ---------------- scratch (device globals; no runtime allocation) ----------
__device__ float g_h   [MROWS*DM];
__device__ float g_xn  [MROWS*DM];
__device__ float g_xz  [MROWS*2*DI];
__device__ float g_xc  [MROWS*DI];
__device__ float g_dbc [MROWS*NDBC];
__device__ float g_dt  [MROWS*DI];
__device__ float g_y   [MROWS*DI];    // gated y = (scan + Dp*xc)*silu(z)
__device__ float g_comb[MROWS*2*DM];
__device__ float g_acc [2];           // loss sum, count

__device__ __forceinline__ float siluf(float x) {
    return x / (1.0f + __expf(-x));
}

// ---------------- init ------------------------------------------------------
__global__ void init_kernel() {
    g_acc[0] = 0.0f; g_acc[1] = 0.0f;
}

// ---------------- embedding gather (optionally time-flipped ids) ------------
__global__ void embed_kernel(const float* __restrict__ emb,
                             const int* __restrict__ ids, int flip) {
    int row = blockIdx.x;               // b*SS + s
    int b = row / SS, s = row % SS;
    int srow = flip ? (b*SS + (SS-1-s)) : row;
    int id = ids[srow];
    const float* src = emb + (size_t)id * DM;
    float* dst = g_h + (size_t)row * DM;
    for (int c = threadIdx.x; c < DM; c += blockDim.x) dst[c] = src[c];
}

// ---------------- RMSNorm: out[..] = x * rsqrt(mean(x^2)+eps) * w -----------
// Writes into out at (maybe flipped row)*ldo + coloff.
__global__ void rmsnorm_kernel(const float* __restrict__ in,
                               const float* __restrict__ w,
                               float* __restrict__ out,
                               int ldo, int coloff, int flip) {
    __shared__ float sh[256];
    int row = blockIdx.x, tid = threadIdx.x;
    const float* x = in + (size_t)row * DM;
    float ss = 0.0f;
    for (int c = tid; c < DM; c += 256) { float v = x[c]; ss += v*v; }
    sh[tid] = ss; __syncthreads();
    for (int s = 128; s > 0; s >>= 1) {
        if (tid < s) sh[tid] += sh[tid+s];
        __syncthreads();
    }
    float scale = rsqrtf(sh[0] / (float)DM + 1e-5f);
    int b = row / SS, s = row % SS;
    int orow = flip ? (b*SS + (SS-1-s)) : row;
    float* o = out + (size_t)orow * ldo + coloff;
    for (int c = tid; c < DM; c += 256) o[c] = x[c] * scale * w[c];
}

// ---------------- generic SGEMM: out[M,N] (+)= X[M,K](lda) @ W[N,K]^T -------
#define BM 64
#define BN 64
#define BK 16
#define GF_ADD 1
#define GF_SOFTPLUS 2

__global__ __launch_bounds__(256)
void gemm_kernel(const float* __restrict__ X, int lda,
                 const float* __restrict__ W,
                 const float* __restrict__ bias,
                 float* __restrict__ out,
                 int M, int N, int K, int flags) {
    __shared__ __align__(16) float As[BK][BM];
    __shared__ __align__(16) float Bs[BK][BN];
    int tid = threadIdx.x;
    int tx = tid & 15, ty = tid >> 4;
    int m0 = blockIdx.y * BM, n0 = blockIdx.x * BN;
    float acc[4][4];
    #pragma unroll
    for (int i = 0; i < 4; i++)
        #pragma unroll
        for (int j = 0; j < 4; j++) acc[i][j] = 0.0f;

    for (int k0 = 0; k0 < K; k0 += BK) {
        #pragma unroll
        for (int it = 0; it < 4; it++) {
            int idx = tid + it * 256;
            int r = idx >> 4, c = idx & 15;
            int gm = m0 + r, gk = k0 + c;
            As[c][r] = (gm < M && gk < K) ? X[(size_t)gm * lda + gk] : 0.0f;
        }
        #pragma unroll
        for (int it = 0; it < 4; it++) {
            int idx = tid + it * 256;
            int r = idx >> 4, c = idx & 15;
            int gn = n0 + r, gk = k0 + c;
            Bs[c][r] = (gn < N && gk < K) ? W[(size_t)gn * K + gk] : 0.0f;
        }
        __syncthreads();
        #pragma unroll
        for (int kk = 0; kk < BK; kk++) {
            float4 a = *(const float4*)&As[kk][ty*4];
            float4 b = *(const float4*)&Bs[kk][tx*4];
            float av[4] = {a.x, a.y, a.z, a.w};
            float bv[4] = {b.x, b.y, b.z, b.w};
            #pragma unroll
            for (int i = 0; i < 4; i++)
                #pragma unroll
                for (int j = 0; j < 4; j++)
                    acc[i][j] = fmaf(av[i], bv[j], acc[i][j]);
        }
        __syncthreads();
    }

    #pragma unroll
    for (int i = 0; i < 4; i++) {
        int gm = m0 + ty*4 + i;
        if (gm >= M) continue;
        #pragma unroll
        for (int j = 0; j < 4; j++) {
            int gn = n0 + tx*4 + j;
            if (gn >= N) continue;
            float v = acc[i][j];
            if (flags & GF_SOFTPLUS) {
                v += bias[gn];
                v = (v > 20.0f) ? v : log1pf(expf(v));
            }
            size_t oi = (size_t)gm * N + gn;
            if (flags & GF_ADD) out[oi] += v;
            else out[oi] = v;
        }
    }
}

// ---------------- causal depthwise conv (K=4) + bias + silu -----------------
__global__ void conv_kernel(const float* __restrict__ convw,
                            const float* __restrict__ convb) {
    int idx = blockIdx.x * blockDim.x + threadIdx.x;
    if (idx >= MROWS * DI) return;
    int row = idx / DI, d = idx % DI;
    int b = row / SS, s = row % SS;
    float acc = convb[d];
    #pragma unroll
    for (int k = 0; k < KC; k++) {
        int sp = s - (KC-1) + k;
        if (sp >= 0)
            acc = fmaf(g_xz[(size_t)(b*SS+sp)*(2*DI) + d], convw[d*KC + k], acc);
    }
    g_xc[idx] = siluf(acc);
}

// ---------------- selective scan --------------------------------------------
// thread -> (b, d, n); n in lane bits [0..3] so shfl.xor 1/2/4/8 reduces over n.
// Writes gated output: (y_scan + Dp*xc) * silu(z)
__global__ void scan_kernel(const float* __restrict__ Alog_l,
                            const float* __restrict__ Dp_l) {
    int tid = blockIdx.x * blockDim.x + threadIdx.x;
    int n = tid & (DS-1);
    int d = (tid / DS) % DI;
    int b = tid / (DS * DI);
    float A = -expf(Alog_l[d*DS + n]);
    float Dp = Dp_l[d];
    float h = 0.0f;
    int base = b * SS;
    for (int t = 0; t < SS; t++) {
        int r = base + t;
        float dt = g_dt[(size_t)r*DI + d];
        float x  = g_xc[(size_t)r*DI + d];
        float Bv = g_dbc[(size_t)r*NDBC + DR + n];
        float Cv = g_dbc[(size_t)r*NDBC + DR + DS + n];
        h = __expf(dt * A) * h + dt * x * Bv;
        float p = h * Cv;
        p += __shfl_xor_sync(0xffffffffu, p, 1);
        p += __shfl_xor_sync(0xffffffffu, p, 2);
        p += __shfl_xor_sync(0xffffffffu, p, 4);
        p += __shfl_xor_sync(0xffffffffu, p, 8);
        if (n == 0) {
            float y = p + Dp * x;
            float z = g_xz[(size_t)r*(2*DI) + DI + d];
            g_y[(size_t)r*DI + d] = y * siluf(z);
        }
    }
}

// ---------------- loss: per-row logsumexp + nll -----------------------------
__global__ void loss_kernel(const float* __restrict__ logits,
                            const int* __restrict__ labels) {
    __shared__ float sh[256];
    int row = blockIdx.x, tid = threadIdx.x;
    const float* rp = logits + (size_t)row * VV;
    float m = -3.4e38f;
    for (int i = tid; i < VV; i += 256) m = fmaxf(m, rp[i]);
    sh[tid] = m; __syncthreads();
    for (int s = 128; s > 0; s >>= 1) {
        if (tid < s) sh[tid] = fmaxf(sh[tid], sh[tid+s]);
        __syncthreads();
    }
    float rowmax = sh[0]; __syncthreads();
    float sum = 0.0f;
    for (int i = tid; i < VV; i += 256) sum += __expf(rp[i] - rowmax);
    sh[tid] = sum; __syncthreads();
    for (int s = 128; s > 0; s >>= 1) {
        if (tid < s) sh[tid] += sh[tid+s];
        __syncthreads();
    }
    if (tid == 0) {
        int lab = labels[row];
        if (lab != -100) {
            float lse = rowmax + logf(sh[0]);
            atomicAdd(&g_acc[0], lse - rp[lab]);   // nll = lse - logit[label]
            atomicAdd(&g_acc[1], 1.0f);
        }
    }
}

__global__ void finalize_kernel(float* __restrict__ out, long long loss_idx) {
    out[loss_idx] = g_acc[0] / fmaxf(g_acc[1], 1.0f);
}

// ---------------- host-side orchestration -----------------------------------
static void launch_gemm(const float* X, int lda, const float* W,
                        const float* bias, float* out,
                        int M, int N, int K, int flags) {
    dim3 grid((N + BN - 1) / BN, (M + BM - 1) / BM);
    gemm_kernel<<<grid, 256>>>(X, lda, W, bias, out, M, N, K, flags);
}

extern "C" void kernel_launch(void* const* d_in, const int* in_sizes, int n_in,
                              void* d_out, int out_size) {
    const int* ids    = (const int*)d_in[0];
    const int* labels = (const int*)d_in[1];
    const float* lm_w = (const float*)d_in[26];
    float* out = (float*)d_out;

    float *h, *xn, *xz, *xc, *dbc, *dt, *y, *comb;
    cudaGetSymbolAddress((void**)&h,    g_h);
    cudaGetSymbolAddress((void**)&xn,   g_xn);
    cudaGetSymbolAddress((void**)&xz,   g_xz);
    cudaGetSymbolAddress((void**)&xc,   g_xc);
    cudaGetSymbolAddress((void**)&dbc,  g_dbc);
    cudaGetSymbolAddress((void**)&dt,   g_dt);
    cudaGetSymbolAddress((void**)&y,    g_y);
    cudaGetSymbolAddress((void**)&comb, g_comb);

    init_kernel<<<1, 1>>>();

    for (int dir = 0; dir < 2; dir++) {
        int base = 2 + dir * 12;
        const float* emb   = (const float*)d_in[base + 0];
        const float* norm  = (const float*)d_in[base + 1];
        const float* inw   = (const float*)d_in[base + 2];
        const float* convw = (const float*)d_in[base + 3];
        const float* convb = (const float*)d_in[base + 4];
        const float* xpw   = (const float*)d_in[base + 5];
        const float* dtw   = (const float*)d_in[base + 6];
        const float* dtb   = (const float*)d_in[base + 7];
        const float* Alog  = (const float*)d_in[base + 8];
        const float* Dp    = (const float*)d_in[base + 9];
        const float* outw  = (const float*)d_in[base + 10];
        const float* fnorm = (const float*)d_in[base + 11];

        embed_kernel<<<MROWS, 256>>>(emb, ids, dir);

        for (int l = 0; l < NL; l++) {
            rmsnorm_kernel<<<MROWS, 256>>>(h, norm + l*DM, xn, DM, 0, 0);
            launch_gemm(xn, DM, inw + (size_t)l*2*DI*DM, nullptr, xz,
                        MROWS, 2*DI, DM, 0);
            conv_kernel<<<(MROWS*DI + 255)/256, 256>>>(convw + l*DI*KC,
                                                       convb + l*DI);
            launch_gemm(xc, DI, xpw + (size_t)l*NDBC*DI, nullptr, dbc,
                        MROWS, NDBC, DI, 0);
            launch_gemm(dbc, NDBC, dtw + (size_t)l*DI*DR, dtb + l*DI, dt,
                        MROWS, DI, DR, GF_SOFTPLUS);
            scan_kernel<<<(BB*DI*DS)/256, 256>>>(Alog + (size_t)l*DI*DS,
                                                 Dp + l*DI);
            launch_gemm(y, DI, outw + (size_t)l*DM*DI, nullptr, h,
                        MROWS, DM, DI, GF_ADD);
        }
        rmsnorm_kernel<<<MROWS, 256>>>(h, fnorm, comb, 2*DM, dir ? DM : 0, dir);
    }

    // logits = comb @ lm_w^T  -> straight into d_out
    launch_gemm(comb, 2*DM, lm_w, nullptr, out, MROWS, VV, 2*DM, 0);

    loss_kernel<<<MROWS, 256>>>(out, labels);

    long long bsv = (long long)MROWS * VV;
    long long loss_idx = (out_size > bsv) ? (long long)out_size - 1 : bsv;
    finalize_kernel<<<1, 1>>>(out, loss_idx);
}

// round 2
// speedup vs baseline: 1.5314x; 1.5314x over previous
#include <cuda_runtime.h>
#include <math.h>
#include <stdint.h>

#define NL 4
#define DM 768
#define DI 1536
#define DS 16
#define DR 48
#define KC 4
#define VV 32000
#define BB 2
#define SS 2048
#define MROWS (BB*SS)          /* 4096 */
#define NDBC (DR+2*DS)         /* 80 */

// ---------------- scratch (device globals; no runtime allocation) ----------
__device__ float g_h   [MROWS*DM];
__device__ float g_xn  [MROWS*DM];
__device__ float g_xz  [MROWS*2*DI];
__device__ float g_xc  [MROWS*DI];
__device__ float g_dbc [MROWS*NDBC];
__device__ float g_dt  [MROWS*DI];
__device__ float g_y   [MROWS*DI];
__device__ float g_comb[MROWS*2*DM];
__device__ float g_acc [2];

__device__ __forceinline__ float siluf(float x) {
    return x / (1.0f + __expf(-x));
}

// ---------------- init ------------------------------------------------------
__global__ void init_kernel() {
    g_acc[0] = 0.0f; g_acc[1] = 0.0f;
}

// ---------------- embedding gather ------------------------------------------
__global__ void embed_kernel(const float* __restrict__ emb,
                             const int* __restrict__ ids, int flip) {
    int row = blockIdx.x;
    int b = row / SS, s = row % SS;
    int srow = flip ? (b*SS + (SS-1-s)) : row;
    int id = ids[srow];
    const float* src = emb + (size_t)id * DM;
    float* dst = g_h + (size_t)row * DM;
    for (int c = threadIdx.x; c < DM; c += blockDim.x) dst[c] = src[c];
}

// ---------------- RMSNorm ----------------------------------------------------
__global__ void rmsnorm_kernel(const float* __restrict__ in,
                               const float* __restrict__ w,
                               float* __restrict__ out,
                               int ldo, int coloff, int flip) {
    __shared__ float sh[256];
    int row = blockIdx.x, tid = threadIdx.x;
    const float* x = in + (size_t)row * DM;
    float ss = 0.0f;
    for (int c = tid; c < DM; c += 256) { float v = x[c]; ss += v*v; }
    sh[tid] = ss; __syncthreads();
    for (int s = 128; s > 0; s >>= 1) {
        if (tid < s) sh[tid] += sh[tid+s];
        __syncthreads();
    }
    float scale = rsqrtf(sh[0] / (float)DM + 1e-5f);
    int b = row / SS, s = row % SS;
    int orow = flip ? (b*SS + (SS-1-s)) : row;
    float* o = out + (size_t)orow * ldo + coloff;
    for (int c = tid; c < DM; c += 256) o[c] = x[c] * scale * w[c];
}

// ---------------- SGEMM: out[M,N] (+)= X[M,K](lda) @ W[N,K]^T ---------------
// 128x128 tile, BK=8, 256 threads, 8x8 per thread (2x2 float4 quadrants),
// double-buffered shared memory. Requires: M % 128 == 0, K % 8 == 0, N % 4 == 0.
#define BM 128
#define BN 128
#define BK 8
#define GF_ADD 1
#define GF_SOFTPLUS 2

__global__ __launch_bounds__(256)
void gemm_kernel(const float* __restrict__ X, int lda,
                 const float* __restrict__ W,
                 const float* __restrict__ bias,
                 float* __restrict__ out,
                 int M, int N, int K, int flags) {
    __shared__ __align__(16) float As[2][BK][BM];
    __shared__ __align__(16) float Bs[2][BK][BN];
    int tid = threadIdx.x;
    int m0 = blockIdx.y * BM, n0 = blockIdx.x * BN;

    // loader mapping: each thread loads one float4 of A and one of B per k-tile
    int lr = tid >> 1;               // 0..127 (tile row)
    int lc = (tid & 1) * 4;          // 0 or 4 (k offset)
    const float* Xp = X + (size_t)(m0 + lr) * lda + lc;
    int gnB = n0 + lr;
    const float* Wp = W + (size_t)gnB * K + lc;
    bool bvalid = (gnB < N);

    // compute mapping
    int tx = tid & 15, ty = tid >> 4;

    float acc[8][8];
    #pragma unroll
    for (int i = 0; i < 8; i++)
        #pragma unroll
        for (int j = 0; j < 8; j++) acc[i][j] = 0.0f;

    int KT = K / BK;

    // prologue: tile 0
    float4 ra = *(const float4*)Xp;
    float4 rb = bvalid ? *(const float4*)Wp : make_float4(0.f,0.f,0.f,0.f);
    As[0][lc+0][lr] = ra.x; As[0][lc+1][lr] = ra.y;
    As[0][lc+2][lr] = ra.z; As[0][lc+3][lr] = ra.w;
    Bs[0][lc+0][lr] = rb.x; Bs[0][lc+1][lr] = rb.y;
    Bs[0][lc+2][lr] = rb.z; Bs[0][lc+3][lr] = rb.w;
    __syncthreads();

    for (int kt = 0; kt < KT; kt++) {
        int cur = kt & 1;
        if (kt + 1 < KT) {
            ra = *(const float4*)(Xp + (size_t)(kt+1) * BK);
            rb = bvalid ? *(const float4*)(Wp + (size_t)(kt+1) * BK)
                        : make_float4(0.f,0.f,0.f,0.f);
        }
        #pragma unroll
        for (int kk = 0; kk < BK; kk++) {
            float4 a0 = *(const float4*)&As[cur][kk][ty*4];
            float4 a1 = *(const float4*)&As[cur][kk][64 + ty*4];
            float4 b0 = *(const float4*)&Bs[cur][kk][tx*4];
            float4 b1 = *(const float4*)&Bs[cur][kk][64 + tx*4];
            float av[8] = {a0.x,a0.y,a0.z,a0.w,a1.x,a1.y,a1.z,a1.w};
            float bv[8] = {b0.x,b0.y,b0.z,b0.w,b1.x,b1.y,b1.z,b1.w};
            #pragma unroll
            for (int i = 0; i < 8; i++)
                #pragma unroll
                for (int j = 0; j < 8; j++)
                    acc[i][j] = fmaf(av[i], bv[j], acc[i][j]);
        }
        if (kt + 1 < KT) {
            int nxt = cur ^ 1;
            As[nxt][lc+0][lr] = ra.x; As[nxt][lc+1][lr] = ra.y;
            As[nxt][lc+2][lr] = ra.z; As[nxt][lc+3][lr] = ra.w;
            Bs[nxt][lc+0][lr] = rb.x; Bs[nxt][lc+1][lr] = rb.y;
            Bs[nxt][lc+2][lr] = rb.z; Bs[nxt][lc+3][lr] = rb.w;
            __syncthreads();
        }
    }

    // epilogue: float4 stores (N % 4 == 0 guaranteed)
    #pragma unroll
    for (int qi = 0; qi < 2; qi++) {
        #pragma unroll
        for (int i = 0; i < 4; i++) {
            int gm = m0 + qi*64 + ty*4 + i;
            int ai = qi*4 + i;
            #pragma unroll
            for (int qj = 0; qj < 2; qj++) {
                int gn = n0 + qj*64 + tx*4;
                if (gn >= N) continue;
                float v0 = acc[ai][qj*4+0], v1 = acc[ai][qj*4+1];
                float v2 = acc[ai][qj*4+2], v3 = acc[ai][qj*4+3];
                size_t oi = (size_t)gm * N + gn;
                if (flags & GF_SOFTPLUS) {
                    v0 += bias[gn+0]; v1 += bias[gn+1];
                    v2 += bias[gn+2]; v3 += bias[gn+3];
                    v0 = (v0 > 20.0f) ? v0 : log1pf(expf(v0));
                    v1 = (v1 > 20.0f) ? v1 : log1pf(expf(v1));
                    v2 = (v2 > 20.0f) ? v2 : log1pf(expf(v2));
                    v3 = (v3 > 20.0f) ? v3 : log1pf(expf(v3));
                }
                if (flags & GF_ADD) {
                    float4 o = *(float4*)&out[oi];
                    v0 += o.x; v1 += o.y; v2 += o.z; v3 += o.w;
                }
                *(float4*)&out[oi] = make_float4(v0, v1, v2, v3);
            }
        }
    }
}

// ---------------- causal depthwise conv (K=4) + bias + silu -----------------
__global__ void conv_kernel(const float* __restrict__ convw,
                            const float* __restrict__ convb) {
    int idx = blockIdx.x * blockDim.x + threadIdx.x;
    if (idx >= MROWS * DI) return;
    int row = idx / DI, d = idx % DI;
    int b = row / SS, s = row % SS;
    float acc = convb[d];
    #pragma unroll
    for (int k = 0; k < KC; k++) {
        int sp = s - (KC-1) + k;
        if (sp >= 0)
            acc = fmaf(g_xz[(size_t)(b*SS+sp)*(2*DI) + d], convw[d*KC + k], acc);
    }
    g_xc[idx] = siluf(acc);
}

// ---------------- selective scan --------------------------------------------
__global__ void scan_kernel(const float* __restrict__ Alog_l,
                            const float* __restrict__ Dp_l) {
    int tid = blockIdx.x * blockDim.x + threadIdx.x;
    int n = tid & (DS-1);
    int d = (tid / DS) % DI;
    int b = tid / (DS * DI);
    float A = -expf(Alog_l[d*DS + n]);
    float Dp = Dp_l[d];
    float h = 0.0f;
    int base = b * SS;
    for (int t = 0; t < SS; t++) {
        int r = base + t;
        float dt = g_dt[(size_t)r*DI + d];
        float x  = g_xc[(size_t)r*DI + d];
        float Bv = g_dbc[(size_t)r*NDBC + DR + n];
        float Cv = g_dbc[(size_t)r*NDBC + DR + DS + n];
        h = __expf(dt * A) * h + dt * x * Bv;
        float p = h * Cv;
        p += __shfl_xor_sync(0xffffffffu, p, 1);
        p += __shfl_xor_sync(0xffffffffu, p, 2);
        p += __shfl_xor_sync(0xffffffffu, p, 4);
        p += __shfl_xor_sync(0xffffffffu, p, 8);
        if (n == 0) {
            float y = p + Dp * x;
            float z = g_xz[(size_t)r*(2*DI) + DI + d];
            g_y[(size_t)r*DI + d] = y * siluf(z);
        }
    }
}

// ---------------- loss -------------------------------------------------------
__global__ void loss_kernel(const float* __restrict__ logits,
                            const int* __restrict__ labels) {
    __shared__ float sh[256];
    int row = blockIdx.x, tid = threadIdx.x;
    const float* rp = logits + (size_t)row * VV;
    float m = -3.4e38f;
    for (int i = tid; i < VV; i += 256) m = fmaxf(m, rp[i]);
    sh[tid] = m; __syncthreads();
    for (int s = 128; s > 0; s >>= 1) {
        if (tid < s) sh[tid] = fmaxf(sh[tid], sh[tid+s]);
        __syncthreads();
    }
    float rowmax = sh[0]; __syncthreads();
    float sum = 0.0f;
    for (int i = tid; i < VV; i += 256) sum += __expf(rp[i] - rowmax);
    sh[tid] = sum; __syncthreads();
    for (int s = 128; s > 0; s >>= 1) {
        if (tid < s) sh[tid] += sh[tid+s];
        __syncthreads();
    }
    if (tid == 0) {
        int lab = labels[row];
        if (lab != -100) {
            float lse = rowmax + logf(sh[0]);
            atomicAdd(&g_acc[0], lse - rp[lab]);
            atomicAdd(&g_acc[1], 1.0f);
        }
    }
}

__global__ void finalize_kernel(float* __restrict__ out, long long loss_idx) {
    out[loss_idx] = g_acc[0] / fmaxf(g_acc[1], 1.0f);
}

// ---------------- host-side orchestration -----------------------------------
static void launch_gemm(const float* X, int lda, const float* W,
                        const float* bias, float* out,
                        int M, int N, int K, int flags) {
    dim3 grid((N + BN - 1) / BN, M / BM);
    gemm_kernel<<<grid, 256>>>(X, lda, W, bias, out, M, N, K, flags);
}

extern "C" void kernel_launch(void* const* d_in, const int* in_sizes, int n_in,
                              void* d_out, int out_size) {
    const int* ids    = (const int*)d_in[0];
    const int* labels = (const int*)d_in[1];
    const float* lm_w = (const float*)d_in[26];
    float* out = (float*)d_out;

    float *h, *xn, *xz, *xc, *dbc, *dt, *y, *comb;
    cudaGetSymbolAddress((void**)&h,    g_h);
    cudaGetSymbolAddress((void**)&xn,   g_xn);
    cudaGetSymbolAddress((void**)&xz,   g_xz);
    cudaGetSymbolAddress((void**)&xc,   g_xc);
    cudaGetSymbolAddress((void**)&dbc,  g_dbc);
    cudaGetSymbolAddress((void**)&dt,   g_dt);
    cudaGetSymbolAddress((void**)&y,    g_y);
    cudaGetSymbolAddress((void**)&comb, g_comb);

    init_kernel<<<1, 1>>>();

    for (int dir = 0; dir < 2; dir++) {
        int base = 2 + dir * 12;
        const float* emb   = (const float*)d_in[base + 0];
        const float* norm  = (const float*)d_in[base + 1];
        const float* inw   = (const float*)d_in[base + 2];
        const float* convw = (const float*)d_in[base + 3];
        const float* convb = (const float*)d_in[base + 4];
        const float* xpw   = (const float*)d_in[base + 5];
        const float* dtw   = (const float*)d_in[base + 6];
        const float* dtb   = (const float*)d_in[base + 7];
        const float* Alog  = (const float*)d_in[base + 8];
        const float* Dp    = (const float*)d_in[base + 9];
        const float* outw  = (const float*)d_in[base + 10];
        const float* fnorm = (const float*)d_in[base + 11];

        embed_kernel<<<MROWS, 256>>>(emb, ids, dir);

        for (int l = 0; l < NL; l++) {
            rmsnorm_kernel<<<MROWS, 256>>>(h, norm + l*DM, xn, DM, 0, 0);
            launch_gemm(xn, DM, inw + (size_t)l*2*DI*DM, nullptr, xz,
                        MROWS, 2*DI, DM, 0);
            conv_kernel<<<(MROWS*DI + 255)/256, 256>>>(convw + l*DI*KC,
                                                       convb + l*DI);
            launch_gemm(xc, DI, xpw + (size_t)l*NDBC*DI, nullptr, dbc,
                        MROWS, NDBC, DI, 0);
            launch_gemm(dbc, NDBC, dtw + (size_t)l*DI*DR, dtb + l*DI, dt,
                        MROWS, DI, DR, GF_SOFTPLUS);
            scan_kernel<<<(BB*DI*DS)/256, 256>>>(Alog + (size_t)l*DI*DS,
                                                 Dp + l*DI);
            launch_gemm(y, DI, outw + (size_t)l*DM*DI, nullptr, h,
                        MROWS, DM, DI, GF_ADD);
        }
        rmsnorm_kernel<<<MROWS, 256>>>(h, fnorm, comb, 2*DM, dir ? DM : 0, dir);
    }

    launch_gemm(comb, 2*DM, lm_w, nullptr, out, MROWS, VV, 2*DM, 0);

    loss_kernel<<<MROWS, 256>>>(out, labels);

    long long bsv = (long long)MROWS * VV;
    long long loss_idx = (out_size > bsv) ? (long long)out_size - 1 : bsv;
    finalize_kernel<<<1, 1>>>(out, loss_idx);
}

// round 4
// speedup vs baseline: 4.0341x; 2.6342x over previous
#include <cuda_runtime.h>
#include <cuda_bf16.h>
#include <math.h>
#include <stdint.h>

#define NL 4
#define DM 768
#define DI 1536
#define DS 16
#define DR 48
#define KC 4
#define VV 32000
#define BB 2
#define SS 2048
#define MROWS (BB*SS)            /* 4096 rows per direction */
#define MTOT  (2*MROWS)          /* 8192 batched rows       */
#define NDBC  (DR+2*DS)          /* 80 */

// ---------------- weight arena offsets (elements) ---------------------------
#define SZ_INW_L  (2*DI*DM)          /* 2359296 */
#define SZ_XPW_L  (NDBC*DI)          /* 122880  */
#define SZ_DTW_L  (DI*DR)            /* 73728   */
#define SZ_OUTW_L (DM*DI)            /* 1179648 */
#define OFF_INW   0
#define OFF_XPW   (NL*SZ_INW_L)                       /* 9437184  */
#define OFF_DTW   (OFF_XPW + NL*SZ_XPW_L)             /* 9928704  */
#define OFF_OUTW  (OFF_DTW + NL*SZ_DTW_L)             /* 10223616 */
#define PD        (OFF_OUTW + NL*SZ_OUTW_L)           /* 14942208 per dir */
#define OFF_LM    (2*PD)                              /* 29884416 */
#define SZ_LM     ((size_t)VV*2*DM)                   /* 49152000 */
#define W_TOTAL   (OFF_LM + SZ_LM)                    /* 79036416 */

// ---------------- scratch (device globals) ----------------------------------
__device__ float g_h   [MTOT*DM];
__device__ float g_xz  [(size_t)MTOT*2*DI];
__device__ float g_xc  [(size_t)MTOT*DI];
__device__ float g_dbc [MTOT*NDBC];
__device__ float g_dt  [(size_t)MTOT*DI];
__device__ float g_acc [2];

__device__ __nv_bfloat16 g_xnh[MTOT*DM],        g_xnl[MTOT*DM];
__device__ __nv_bfloat16 g_xch[(size_t)MTOT*DI],g_xcl[(size_t)MTOT*DI];
__device__ __nv_bfloat16 g_dbh[MTOT*NDBC],      g_dbl[MTOT*NDBC];
__device__ __nv_bfloat16 g_yh [(size_t)MTOT*DI],g_yl [(size_t)MTOT*DI];
__device__ __nv_bfloat16 g_cbh[MROWS*2*DM],     g_cbl[MROWS*2*DM];
__device__ __nv_bfloat16 g_wh [W_TOTAL],        g_wl [W_TOTAL];

__device__ __forceinline__ float siluf(float x) {
    return x / (1.0f + __expf(-x));
}

__device__ __forceinline__ void splitbf(float v, __nv_bfloat16& h, __nv_bfloat16& l) {
    h = __float2bfloat16(v);
    l = __float2bfloat16(v - __bfloat162float(h));
}

// ---------------- init ------------------------------------------------------
__global__ void init_kernel() { g_acc[0] = 0.0f; g_acc[1] = 0.0f; }

// ---------------- fp32 -> bf16 hi/lo converter ------------------------------
__global__ void cvt_kernel(const float* __restrict__ src,
                           __nv_bfloat16* __restrict__ dh,
                           __nv_bfloat16* __restrict__ dl, long n4) {
    long i = blockIdx.x * (long)blockDim.x + threadIdx.x;
    long stride = (long)gridDim.x * blockDim.x;
    for (; i < n4; i += stride) {
        float4 v = ((const float4*)src)[i];
        __nv_bfloat16 h0,h1,h2,h3,l0,l1,l2,l3;
        splitbf(v.x,h0,l0); splitbf(v.y,h1,l1);
        splitbf(v.z,h2,l2); splitbf(v.w,h3,l3);
        ushort4 ph = make_ushort4(*(uint16_t*)&h0,*(uint16_t*)&h1,
                                  *(uint16_t*)&h2,*(uint16_t*)&h3);
        ushort4 pl = make_ushort4(*(uint16_t*)&l0,*(uint16_t*)&l1,
                                  *(uint16_t*)&l2,*(uint16_t*)&l3);
        ((ushort4*)dh)[i] = ph;
        ((ushort4*)dl)[i] = pl;
    }
}

// ---------------- embedding (both dirs) --------------------------------------
__global__ void embed_kernel(const float* __restrict__ emb0,
                             const float* __restrict__ emb1,
                             const int* __restrict__ ids) {
    int row = blockIdx.x;                 // 0..8191
    int dir = row >> 12;
    int r = row & (MROWS-1);
    int b = r >> 11, s = r & (SS-1);
    int srow = b*SS + (dir ? (SS-1-s) : s);
    const float* emb = dir ? emb1 : emb0;
    const float* src = emb + (size_t)ids[srow] * DM;
    float* dst = g_h + (size_t)row * DM;
    for (int c = threadIdx.x; c < DM; c += blockDim.x) dst[c] = src[c];
}

// ---------------- RMSNorm (batched; emits bf16 hi/lo) ------------------------
// final=0: out hi/lo at row*DM.  final=1: comb layout with flip + col offset.
__global__ void rmsnorm_kernel(const float* __restrict__ w0,
                               const float* __restrict__ w1,
                               __nv_bfloat16* __restrict__ oh,
                               __nv_bfloat16* __restrict__ ol,
                               int final_flag) {
    __shared__ float sh[256];
    int row = blockIdx.x, tid = threadIdx.x;
    int dir = row >> 12;
    const float* w = dir ? w1 : w0;
    const float* x = g_h + (size_t)row * DM;
    float ss = 0.0f;
    for (int c = tid; c < DM; c += 256) { float v = x[c]; ss += v*v; }
    sh[tid] = ss; __syncthreads();
    for (int s = 128; s > 0; s >>= 1) {
        if (tid < s) sh[tid] += sh[tid+s];
        __syncthreads();
    }
    float scale = rsqrtf(sh[0] / (float)DM + 1e-5f);
    size_t obase; int ldo;
    if (!final_flag) { obase = (size_t)row * DM; ldo = 1; }
    else {
        int r = row & (MROWS-1);
        int b = r >> 11, s = r & (SS-1);
        int orow = dir ? (b*SS + (SS-1-s)) : r;
        obase = (size_t)orow * (2*DM) + dir*DM; ldo = 1;
    }
    for (int c = tid; c < DM; c += 256) {
        float v = x[c] * scale * w[c];
        __nv_bfloat16 h, l; splitbf(v, h, l);
        oh[obase + c*ldo] = h; ol[obase + c*ldo] = l;
    }
}

// =============================================================================
// split-bf16 mma.sync GEMM: out[Mtot,N] (+)= A[Mtot,K](ldk) @ W[N,K]^T
// 128x128 tile, BK=32, 256 threads, warp tile 32x64, cp.async double buffer.
// =============================================================================
#define GF_ADD 1
#define GF_SOFTPLUS 2
#define GF_EMIT 4

#define RA_H 0
#define RA_L 10240
#define RB_H 20480
#define RB_L 30720
#define STG  40960
#define SMEM_GEMM (2*STG)

__device__ __forceinline__ uint32_t smem_u32(const void* p) {
    uint32_t a;
    asm("{ .reg .u64 t; cvta.to.shared.u64 t, %1; cvt.u32.u64 %0, t; }"
        : "=r"(a) : "l"(p));
    return a;
}

#define CPA16(dst, src, sz) \
    asm volatile("cp.async.cg.shared.global [%0], [%1], 16, %2;" \
                 :: "r"(dst), "l"(src), "r"(sz))

#define LDSM4(r, addr) \
    asm volatile("ldmatrix.sync.aligned.m8n8.x4.shared.b16 {%0,%1,%2,%3}, [%4];" \
                 : "=r"((r)[0]), "=r"((r)[1]), "=r"((r)[2]), "=r"((r)[3]) : "r"(addr))

#define MMA(d, a, b0r, b1r) \
    asm volatile("mma.sync.aligned.m16n8k16.row.col.f32.bf16.bf16.f32 " \
                 "{%0,%1,%2,%3},{%4,%5,%6,%7},{%8,%9},{%0,%1,%2,%3};" \
                 : "+f"((d)[0]), "+f"((d)[1]), "+f"((d)[2]), "+f"((d)[3]) \
                 : "r"((a)[0]), "r"((a)[1]), "r"((a)[2]), "r"((a)[3]), \
                   "r"(b0r), "r"(b1r))

__global__ __launch_bounds__(256)
void tgemm_kernel(const __nv_bfloat16* __restrict__ Ah,
                  const __nv_bfloat16* __restrict__ Al, int ldk,
                  const __nv_bfloat16* __restrict__ Bh0,
                  const __nv_bfloat16* __restrict__ Bl0,
                  const __nv_bfloat16* __restrict__ Bh1,
                  const __nv_bfloat16* __restrict__ Bl1,
                  const float* __restrict__ bias0,
                  const float* __restrict__ bias1,
                  float* __restrict__ out,
                  __nv_bfloat16* __restrict__ Eh,
                  __nv_bfloat16* __restrict__ El,
                  int N, int K, int flags, int mhalf) {
    extern __shared__ __align__(16) char smem[];
    uint32_t sb = smem_u32(smem);
    int tid = threadIdx.x;
    int lane = tid & 31, wid = tid >> 5;
    int m0 = blockIdx.y * 128, n0 = blockIdx.x * 128;

    const __nv_bfloat16* Bh = Bh0; const __nv_bfloat16* Bl = Bl0;
    const float* bias = bias0;
    if (mhalf && m0 >= mhalf) { Bh = Bh1; Bl = Bl1; bias = bias1; }

    // loader mapping
    int lrow = tid >> 1, khalf = (tid & 1) * 16;
    const __nv_bfloat16* Agh = Ah + (size_t)(m0 + lrow) * ldk + khalf;
    const __nv_bfloat16* Agl = Al + (size_t)(m0 + lrow) * ldk + khalf;
    int gnB = n0 + lrow;
    int bvalid = (gnB < N);
    const __nv_bfloat16* Bgh = Bh + (size_t)gnB * K + khalf;
    const __nv_bfloat16* Bgl = Bl + (size_t)gnB * K + khalf;
    uint32_t sdst = sb + lrow * 80 + khalf * 2;

    int NKC = (K + 31) / 32;

    // compute mapping
    int wm = (wid & 3) * 32, wn = (wid >> 2) * 64;
    float acc[2][8][4];
    #pragma unroll
    for (int mi = 0; mi < 2; mi++)
        #pragma unroll
        for (int ni = 0; ni < 8; ni++)
            #pragma unroll
            for (int q = 0; q < 4; q++) acc[mi][ni][q] = 0.0f;

    // ---- issue one chunk's cp.async group
    #define ISSUE(kc_) do {                                                  \
        int st_ = (kc_) & 1;                                                 \
        uint32_t s0_ = sdst + st_ * STG;                                     \
        int kb_ = (kc_) * 32;                                                \
        _Pragma("unroll")                                                    \
        for (int hf = 0; hf < 2; hf++) {                                     \
            int k_ = kb_ + khalf + hf * 8;                                   \
            int asz = (k_ < K) ? 16 : 0;                                     \
            int bsz = (bvalid && k_ < K) ? 16 : 0;                           \
            CPA16(s0_ + RA_H + hf*16, Agh + kb_ + hf*8, asz);                \
            CPA16(s0_ + RA_L + hf*16, Agl + kb_ + hf*8, asz);                \
            CPA16(s0_ + RB_H + hf*16, Bgh + kb_ + hf*8, bsz);                \
            CPA16(s0_ + RB_L + hf*16, Bgl + kb_ + hf*8, bsz);                \
        }                                                                    \
        asm volatile("cp.async.commit_group;" ::: "memory");                 \
    } while (0)

    ISSUE(0);
    for (int kc = 0; kc < NKC; kc++) {
        if (kc + 1 < NKC) {
            ISSUE(kc + 1);
            asm volatile("cp.async.wait_group 1;" ::: "memory");
        } else {
            asm volatile("cp.async.wait_group 0;" ::: "memory");
        }
        __syncthreads();

        uint32_t ab = sb + (kc & 1) * STG;
        uint32_t lrowsel = (lane & 15);
        #pragma unroll
        for (int ks = 0; ks < 2; ks++) {
            uint32_t kof2 = (ks*16 + ((lane >> 4) << 3)) * 2;
            uint32_t ah[2][4], al2[2][4];
            #pragma unroll
            for (int mi = 0; mi < 2; mi++) {
                uint32_t ro = (wm + mi*16 + lrowsel) * 80 + kof2;
                LDSM4(ah[mi],  ab + RA_H + ro);
                LDSM4(al2[mi], ab + RA_L + ro);
            }
            #pragma unroll
            for (int nip = 0; nip < 4; nip++) {
                uint32_t ro = (wn + nip*16 + lrowsel) * 80 + kof2;
                uint32_t bh[4], bl2[4];
                LDSM4(bh,  ab + RB_H + ro);
                LDSM4(bl2, ab + RB_L + ro);
                #pragma unroll
                for (int mi = 0; mi < 2; mi++) {
                    MMA(acc[mi][nip*2],   ah[mi],  bh[0],  bh[2]);
                    MMA(acc[mi][nip*2],   ah[mi],  bl2[0], bl2[2]);
                    MMA(acc[mi][nip*2],   al2[mi], bh[0],  bh[2]);
                    MMA(acc[mi][nip*2+1], ah[mi],  bh[1],  bh[3]);
                    MMA(acc[mi][nip*2+1], ah[mi],  bl2[1], bl2[3]);
                    MMA(acc[mi][nip*2+1], al2[mi], bh[1],  bh[3]);
                }
            }
        }
        __syncthreads();
    }

    // epilogue
    #pragma unroll
    for (int mi = 0; mi < 2; mi++) {
        int gr = m0 + wm + mi*16 + (lane >> 2);
        #pragma unroll
        for (int ni = 0; ni < 8; ni++) {
            int c = n0 + wn + ni*8 + (lane & 3)*2;
            if (c >= N) continue;
            #pragma unroll
            for (int half = 0; half < 2; half++) {
                int row = gr + half*8;
                float v0 = acc[mi][ni][half*2+0];
                float v1 = acc[mi][ni][half*2+1];
                if (flags & GF_SOFTPLUS) {
                    v0 += bias[c]; v1 += bias[c+1];
                    v0 = (v0 > 20.0f) ? v0 : log1pf(expf(v0));
                    v1 = (v1 > 20.0f) ? v1 : log1pf(expf(v1));
                }
                size_t oi = (size_t)row * N + c;
                if (flags & GF_ADD) {
                    float2 o = *(float2*)&out[oi];
                    v0 += o.x; v1 += o.y;
                }
                *(float2*)&out[oi] = make_float2(v0, v1);
                if (flags & GF_EMIT) {
                    __nv_bfloat16 h0,l0,h1,l1;
                    splitbf(v0,h0,l0); splitbf(v1,h1,l1);
                    Eh[oi] = h0; Eh[oi+1] = h1;
                    El[oi] = l0; El[oi+1] = l1;
                }
            }
        }
    }
}

// ---------------- causal depthwise conv + bias + silu (batched dirs) --------
__global__ void conv_kernel(const float* __restrict__ cw0,
                            const float* __restrict__ cw1,
                            const float* __restrict__ cb0,
                            const float* __restrict__ cb1) {
    size_t idx = (size_t)blockIdx.x * blockDim.x + threadIdx.x;
    if (idx >= (size_t)MTOT * DI) return;
    int row = (int)(idx / DI), d = (int)(idx % DI);
    int dir = row >> 12;
    int s = row & (SS-1);
    int rowbase = row - s;
    const float* cw = dir ? cw1 : cw0;
    const float* cb = dir ? cb1 : cb0;
    float acc = cb[d];
    #pragma unroll
    for (int k = 0; k < KC; k++) {
        int sp = s - (KC-1) + k;
        if (sp >= 0)
            acc = fmaf(g_xz[(size_t)(rowbase+sp)*(2*DI) + d], cw[d*KC + k], acc);
    }
    float v = siluf(acc);
    g_xc[idx] = v;
    __nv_bfloat16 h, l; splitbf(v, h, l);
    g_xch[idx] = h; g_xcl[idx] = l;
}

// ---------------- selective scan (batched dirs, prefetch-pipelined) ---------
__global__ void scan_kernel(const float* __restrict__ Alog0,
                            const float* __restrict__ Alog1,
                            const float* __restrict__ Dp0,
                            const float* __restrict__ Dp1) {
    int tid = blockIdx.x * blockDim.x + threadIdx.x;
    int n = tid & (DS-1);
    int d = (tid >> 4) % DI;
    int bb = tid / (DS * DI);           // 0..3; dir = bb>>1
    const float* Alog = (bb >= 2) ? Alog1 : Alog0;
    const float* Dpp  = (bb >= 2) ? Dp1  : Dp0;
    float A = -expf(Alog[d*DS + n]);
    float Dp = Dpp[d];
    float h = 0.0f;
    size_t base = (size_t)bb * SS;

    size_t r = base;
    float dt = g_dt [r*DI + d];
    float x  = g_xc [r*DI + d];
    float Bv = g_dbc[r*NDBC + DR + n];
    float Cv = g_dbc[r*NDBC + DR + DS + n];
    float z  = g_xz [r*(2*DI) + DI + d];

    for (int t = 0; t < SS; t++) {
        float dtn=0.f, xn_=0.f, Bvn=0.f, Cvn=0.f, zn=0.f;
        if (t + 1 < SS) {
            size_t r2 = base + t + 1;
            dtn = g_dt [r2*DI + d];
            xn_ = g_xc [r2*DI + d];
            Bvn = g_dbc[r2*NDBC + DR + n];
            Cvn = g_dbc[r2*NDBC + DR + DS + n];
            zn  = g_xz [r2*(2*DI) + DI + d];
        }
        h = __expf(dt * A) * h + dt * x * Bv;
        float p = h * Cv;
        p += __shfl_xor_sync(0xffffffffu, p, 1);
        p += __shfl_xor_sync(0xffffffffu, p, 2);
        p += __shfl_xor_sync(0xffffffffu, p, 4);
        p += __shfl_xor_sync(0xffffffffu, p, 8);
        if (n == 0) {
            float y = (p + Dp * x) * siluf(z);
            size_t yi = (base + t)*DI + d;
            __nv_bfloat16 hh, ll; splitbf(y, hh, ll);
            g_yh[yi] = hh; g_yl[yi] = ll;
        }
        dt = dtn; x = xn_; Bv = Bvn; Cv = Cvn; z = zn;
    }
}

// ---------------- loss -------------------------------------------------------
__global__ void loss_kernel(const float* __restrict__ logits,
                            const int* __restrict__ labels) {
    __shared__ float sh[256];
    int row = blockIdx.x, tid = threadIdx.x;
    const float* rp = logits + (size_t)row * VV;
    float m = -3.4e38f;
    for (int i = tid; i < VV; i += 256) m = fmaxf(m, rp[i]);
    sh[tid] = m; __syncthreads();
    for (int s = 128; s > 0; s >>= 1) {
        if (tid < s) sh[tid] = fmaxf(sh[tid], sh[tid+s]);
        __syncthreads();
    }
    float rowmax = sh[0]; __syncthreads();
    float sum = 0.0f;
    for (int i = tid; i < VV; i += 256) sum += __expf(rp[i] - rowmax);
    sh[tid] = sum; __syncthreads();
    for (int s = 128; s > 0; s >>= 1) {
        if (tid < s) sh[tid] += sh[tid+s];
        __syncthreads();
    }
    if (tid == 0) {
        int lab = labels[row];
        if (lab != -100) {
            float lse = rowmax + logf(sh[0]);
            atomicAdd(&g_acc[0], lse - rp[lab]);
            atomicAdd(&g_acc[1], 1.0f);
        }
    }
}

__global__ void finalize_kernel(float* __restrict__ out, long long loss_idx) {
    out[loss_idx] = g_acc[0] / fmaxf(g_acc[1], 1.0f);
}

// ---------------- host-side orchestration -----------------------------------
static void launch_gemm(const __nv_bfloat16* Ah, const __nv_bfloat16* Al, int ldk,
                        const __nv_bfloat16* Bh0, const __nv_bfloat16* Bl0,
                        const __nv_bfloat16* Bh1, const __nv_bfloat16* Bl1,
                        const float* bias0, const float* bias1,
                        float* out, __nv_bfloat16* Eh, __nv_bfloat16* El,
                        int Mtot, int N, int K, int flags, int mhalf) {
    dim3 grid((N + 127) / 128, Mtot / 128);
    tgemm_kernel<<<grid, 256, SMEM_GEMM>>>(Ah, Al, ldk, Bh0, Bl0, Bh1, Bl1,
                                           bias0, bias1, out, Eh, El,
                                           N, K, flags, mhalf);
}

static void launch_cvt(const float* src, __nv_bfloat16* dh, __nv_bfloat16* dl,
                       long n) {
    long n4 = n / 4;
    int blocks = (int)((n4 + 255) / 256);
    if (blocks > 2048) blocks = 2048;
    cvt_kernel<<<blocks, 256>>>(src, dh, dl, n4);
}

extern "C" void kernel_launch(void* const* d_in, const int* in_sizes, int n_in,
                              void* d_out, int out_size) {
    const int* ids    = (const int*)d_in[0];
    const int* labels = (const int*)d_in[1];
    const float* lm_w = (const float*)d_in[26];
    float* out = (float*)d_out;

    cudaFuncSetAttribute(tgemm_kernel,
                         cudaFuncAttributeMaxDynamicSharedMemorySize, SMEM_GEMM);

    float *h, *xz, *xc, *dbc, *dt;
    __nv_bfloat16 *xnh, *xnl, *xch, *xcl, *dbh, *dbl, *yh, *yl, *cbh, *cbl, *wh, *wl;
    cudaGetSymbolAddress((void**)&h,   g_h);
    cudaGetSymbolAddress((void**)&xz,  g_xz);
    cudaGetSymbolAddress((void**)&xc,  g_xc);
    cudaGetSymbolAddress((void**)&dbc, g_dbc);
    cudaGetSymbolAddress((void**)&dt,  g_dt);
    cudaGetSymbolAddress((void**)&xnh, g_xnh);
    cudaGetSymbolAddress((void**)&xnl, g_xnl);
    cudaGetSymbolAddress((void**)&xch, g_xch);
    cudaGetSymbolAddress((void**)&xcl, g_xcl);
    cudaGetSymbolAddress((void**)&dbh, g_dbh);
    cudaGetSymbolAddress((void**)&dbl, g_dbl);
    cudaGetSymbolAddress((void**)&yh,  g_yh);
    cudaGetSymbolAddress((void**)&yl,  g_yl);
    cudaGetSymbolAddress((void**)&cbh, g_cbh);
    cudaGetSymbolAddress((void**)&cbl, g_cbl);
    cudaGetSymbolAddress((void**)&wh,  g_wh);
    cudaGetSymbolAddress((void**)&wl,  g_wl);

    init_kernel<<<1, 1>>>();

    // convert all weights to bf16 hi/lo
    for (int dir = 0; dir < 2; dir++) {
        int base = 2 + dir * 12;
        size_t ab = (size_t)dir * PD;
        launch_cvt((const float*)d_in[base + 2], wh + ab + OFF_INW,
                   wl + ab + OFF_INW,  (long)NL * SZ_INW_L);
        launch_cvt((const float*)d_in[base + 5], wh + ab + OFF_XPW,
                   wl + ab + OFF_XPW,  (long)NL * SZ_XPW_L);
        launch_cvt((const float*)d_in[base + 6], wh + ab + OFF_DTW,
                   wl + ab + OFF_DTW,  (long)NL * SZ_DTW_L);
        launch_cvt((const float*)d_in[base + 10], wh + ab + OFF_OUTW,
                   wl + ab + OFF_OUTW, (long)NL * SZ_OUTW_L);
    }
    launch_cvt(lm_w, wh + OFF_LM, wl + OFF_LM, (long)SZ_LM);

    const float* emb0   = (const float*)d_in[2];
    const float* emb1   = (const float*)d_in[14];
    const float* norm0  = (const float*)d_in[3];
    const float* norm1  = (const float*)d_in[15];
    const float* cw0    = (const float*)d_in[5];
    const float* cw1    = (const float*)d_in[17];
    const float* cb0    = (const float*)d_in[6];
    const float* cb1    = (const float*)d_in[18];
    const float* dtb0   = (const float*)d_in[9];
    const float* dtb1   = (const float*)d_in[21];
    const float* Alog0  = (const float*)d_in[10];
    const float* Alog1  = (const float*)d_in[22];
    const float* Dp0    = (const float*)d_in[11];
    const float* Dp1    = (const float*)d_in[23];
    const float* fn0    = (const float*)d_in[13];
    const float* fn1    = (const float*)d_in[25];

    embed_kernel<<<MTOT, 256>>>(emb0, emb1, ids);

    for (int l = 0; l < NL; l++) {
        size_t w0 = 0, w1 = PD;
        rmsnorm_kernel<<<MTOT, 256>>>(norm0 + l*DM, norm1 + l*DM, xnh, xnl, 0);

        launch_gemm(xnh, xnl, DM,
                    wh + w0 + OFF_INW + (size_t)l*SZ_INW_L,
                    wl + w0 + OFF_INW + (size_t)l*SZ_INW_L,
                    wh + w1 + OFF_INW + (size_t)l*SZ_INW_L,
                    wl + w1 + OFF_INW + (size_t)l*SZ_INW_L,
                    nullptr, nullptr, xz, nullptr, nullptr,
                    MTOT, 2*DI, DM, 0, MROWS);

        conv_kernel<<<((size_t)MTOT*DI + 255)/256, 256>>>(
            cw0 + l*DI*KC, cw1 + l*DI*KC, cb0 + l*DI, cb1 + l*DI);

        launch_gemm(xch, xcl, DI,
                    wh + w0 + OFF_XPW + (size_t)l*SZ_XPW_L,
                    wl + w0 + OFF_XPW + (size_t)l*SZ_XPW_L,
                    wh + w1 + OFF_XPW + (size_t)l*SZ_XPW_L,
                    wl + w1 + OFF_XPW + (size_t)l*SZ_XPW_L,
                    nullptr, nullptr, dbc, dbh, dbl,
                    MTOT, NDBC, DI, GF_EMIT, MROWS);

        launch_gemm(dbh, dbl, NDBC,
                    wh + w0 + OFF_DTW + (size_t)l*SZ_DTW_L,
                    wl + w0 + OFF_DTW + (size_t)l*SZ_DTW_L,
                    wh + w1 + OFF_DTW + (size_t)l*SZ_DTW_L,
                    wl + w1 + OFF_DTW + (size_t)l*SZ_DTW_L,
                    dtb0 + l*DI, dtb1 + l*DI, dt, nullptr, nullptr,
                    MTOT, DI, DR, GF_SOFTPLUS, MROWS);

        scan_kernel<<<(2*BB*DI*DS)/256, 256>>>(Alog0 + (size_t)l*DI*DS,
                                               Alog1 + (size_t)l*DI*DS,
                                               Dp0 + l*DI, Dp1 + l*DI);

        launch_gemm(yh, yl, DI,
                    wh + w0 + OFF_OUTW + (size_t)l*SZ_OUTW_L,
                    wl + w0 + OFF_OUTW + (size_t)l*SZ_OUTW_L,
                    wh + w1 + OFF_OUTW + (size_t)l*SZ_OUTW_L,
                    wl + w1 + OFF_OUTW + (size_t)l*SZ_OUTW_L,
                    nullptr, nullptr, h, nullptr, nullptr,
                    MTOT, DM, DI, GF_ADD, MROWS);
    }

    rmsnorm_kernel<<<MTOT, 256>>>(fn0, fn1, cbh, cbl, 1);

    launch_gemm(cbh, cbl, 2*DM,
                wh + OFF_LM, wl + OFF_LM, wh + OFF_LM, wl + OFF_LM,
                nullptr, nullptr, out, nullptr, nullptr,
                MROWS, VV, 2*DM, 0, 0);

    loss_kernel<<<MROWS, 256>>>(out, labels);

    long long bsv = (long long)MROWS * VV;
    long long loss_idx = (out_size > bsv) ? (long long)out_size - 1 : bsv;
    finalize_kernel<<<1, 1>>>(out, loss_idx);
}